// round 4
// baseline (speedup 1.0000x reference)
#include <cuda_runtime.h>
#include <cuda_bf16.h>
#include <math.h>
#include <stdint.h>

#define T_    2048
#define HID_  4096
#define H_    32
#define HKV_  8
#define D_    128
#define NQKV_ 6144
#define WIN_  1024

// ---------------- scratch ---------------------------------------------------
__device__ float g_qkv [T_ * NQKV_];
__device__ float g_q   [T_ * H_ * D_];      // [t][h][d]
__device__ float g_k   [T_ * HKV_ * D_];    // [t][kh][d]
__device__ float g_attn[T_ * H_ * D_];
__device__ float g_cos [T_ * 64];
__device__ float g_sin [T_ * 64];

// ---------------- helpers ---------------------------------------------------
__device__ __forceinline__ void mma_bf16(float* d, const uint32_t* a,
                                         const uint32_t* b) {
  asm volatile(
      "mma.sync.aligned.m16n8k16.row.col.f32.bf16.bf16.f32 "
      "{%0,%1,%2,%3}, {%4,%5,%6,%7}, {%8,%9}, {%0,%1,%2,%3};"
      : "+f"(d[0]), "+f"(d[1]), "+f"(d[2]), "+f"(d[3])
      : "r"(a[0]), "r"(a[1]), "r"(a[2]), "r"(a[3]), "r"(b[0]), "r"(b[1]));
}
__device__ __forceinline__ void splitf(float x, __nv_bfloat16& h,
                                       __nv_bfloat16& l) {
  h = __float2bfloat16(x);
  l = __float2bfloat16(x - __bfloat162float(h));
}
__device__ __forceinline__ uint32_t pk(__nv_bfloat16 a, __nv_bfloat16 b) {
  __nv_bfloat162 t(a, b);
  return *reinterpret_cast<uint32_t*>(&t);
}

// ---------------- bf16x3 GEMM: C[M,N] = A[M,K] @ B[K,N] --------------------
// BM=BN=128, BK=32, 256 threads (8 warps 2x4, 64x32 warp tiles),
// register-staged global prefetch, smem pre-split bf16 hi/lo.
#define AS_STR 40   // halves; banks (20r+c)%32 distinct within a warp quad-map
__global__ __launch_bounds__(256)
void bf16x3_gemm(const float* __restrict__ A, const float* __restrict__ B,
                 float* __restrict__ C, int M, int N, int K) {
  __shared__ __nv_bfloat16 Ah[128 * AS_STR], Al[128 * AS_STR];
  __shared__ __nv_bfloat16 Bh[128 * AS_STR], Bl[128 * AS_STR];
  const int tid = threadIdx.x, lane = tid & 31, warp = tid >> 5;
  const int wm = warp & 1, wn = warp >> 1;
  const int gr = lane >> 2, cq = lane & 3;
  const int cRow = blockIdx.y * 128, cCol = blockIdx.x * 128;

  float acc[4][4][4];
#pragma unroll
  for (int mt = 0; mt < 4; mt++)
#pragma unroll
    for (int nt = 0; nt < 4; nt++)
#pragma unroll
      for (int r = 0; r < 4; r++) acc[mt][nt][r] = 0.f;

  const int ar = tid >> 1, acs = (tid & 1) * 16;   // A: 128 rows x 32 cols
  const int bk = tid >> 3, bns = (tid & 7) * 16;   // B: 32 rows x 128 cols
  const float* Ap = A + (size_t)(cRow + ar) * K + acs;
  const float* Bp = B + (size_t)bk * N + cCol + bns;

  float a_st[16], b_st[16];
#pragma unroll
  for (int i = 0; i < 4; i++) {
    *(float4*)&a_st[i * 4] = *(const float4*)(Ap + i * 4);
    *(float4*)&b_st[i * 4] = *(const float4*)(Bp + i * 4);
  }

  for (int k0 = 0; k0 < K; k0 += 32) {
    // stage -> smem (split)
#pragma unroll
    for (int i = 0; i < 16; i++) {
      __nv_bfloat16 h, l;
      splitf(a_st[i], h, l);
      Ah[ar * AS_STR + acs + i] = h;
      Al[ar * AS_STR + acs + i] = l;
      splitf(b_st[i], h, l);
      Bh[(bns + i) * AS_STR + bk] = h;   // transposed: [n][k]
      Bl[(bns + i) * AS_STR + bk] = l;
    }
    __syncthreads();
    if (k0 + 32 < K) {
#pragma unroll
      for (int i = 0; i < 4; i++) {
        *(float4*)&a_st[i * 4] = *(const float4*)(Ap + k0 + 32 + i * 4);
        *(float4*)&b_st[i * 4] =
            *(const float4*)(Bp + (size_t)(k0 + 32) * N + i * 4);
      }
    }
#pragma unroll
    for (int ks = 0; ks < 2; ks++) {
      uint32_t ah[4][4], al[4][4], bh[4][2], bl[4][2];
#pragma unroll
      for (int mt = 0; mt < 4; mt++) {
        int base = (wm * 64 + mt * 16 + gr) * AS_STR + ks * 16 + cq * 2;
        ah[mt][0] = *(uint32_t*)&Ah[base];
        ah[mt][1] = *(uint32_t*)&Ah[base + 8 * AS_STR];
        ah[mt][2] = *(uint32_t*)&Ah[base + 8];
        ah[mt][3] = *(uint32_t*)&Ah[base + 8 * AS_STR + 8];
        al[mt][0] = *(uint32_t*)&Al[base];
        al[mt][1] = *(uint32_t*)&Al[base + 8 * AS_STR];
        al[mt][2] = *(uint32_t*)&Al[base + 8];
        al[mt][3] = *(uint32_t*)&Al[base + 8 * AS_STR + 8];
      }
#pragma unroll
      for (int nt = 0; nt < 4; nt++) {
        int base = (wn * 32 + nt * 8 + gr) * AS_STR + ks * 16 + cq * 2;
        bh[nt][0] = *(uint32_t*)&Bh[base];
        bh[nt][1] = *(uint32_t*)&Bh[base + 8];
        bl[nt][0] = *(uint32_t*)&Bl[base];
        bl[nt][1] = *(uint32_t*)&Bl[base + 8];
      }
#pragma unroll
      for (int mt = 0; mt < 4; mt++)
#pragma unroll
        for (int nt = 0; nt < 4; nt++) {
          mma_bf16(acc[mt][nt], ah[mt], bh[nt]);
          mma_bf16(acc[mt][nt], ah[mt], bl[nt]);
          mma_bf16(acc[mt][nt], al[mt], bh[nt]);
        }
    }
    __syncthreads();
  }

#pragma unroll
  for (int mt = 0; mt < 4; mt++) {
    int r = cRow + wm * 64 + mt * 16 + gr;
#pragma unroll
    for (int nt = 0; nt < 4; nt++) {
      int c = cCol + wn * 32 + nt * 8 + cq * 2;
      *(float2*)&C[(size_t)r * N + c] =
          make_float2(acc[mt][nt][0], acc[mt][nt][1]);
      *(float2*)&C[(size_t)(r + 8) * N + c] =
          make_float2(acc[mt][nt][2], acc[mt][nt][3]);
    }
  }
}

// ---------------- RoPE table (fp64 once, tiny) ------------------------------
__global__ void rope_table_kernel(const int* __restrict__ positions) {
  int t = blockIdx.x, i = threadIdx.x;
  double inv_freq = pow(1000000.0, -(double)i / 64.0);
  double ang = (double)positions[t] * inv_freq;
  double sd, cd;
  sincos(ang, &sd, &cd);
  g_cos[t * 64 + i] = (float)cd;
  g_sin[t * 64 + i] = (float)sd;
}

// ---------------- fused RMSNorm + NeoX RoPE --------------------------------
__global__ void norm_rope_kernel(const float* __restrict__ qkv,
                                 const float* __restrict__ qw,
                                 const float* __restrict__ kw,
                                 float* __restrict__ qout,
                                 float* __restrict__ kout) {
  const int t = blockIdx.x, head = blockIdx.y, d = threadIdx.x;
  const bool isq = head < H_;
  float x = qkv[(size_t)t * NQKV_ + head * D_ + d];

  __shared__ float red[4];
  __shared__ float xs[D_];
  float ss = x * x;
#pragma unroll
  for (int m = 16; m; m >>= 1) ss += __shfl_xor_sync(0xffffffffu, ss, m);
  if ((d & 31) == 0) red[d >> 5] = ss;
  __syncthreads();
  float var = (red[0] + red[1] + red[2] + red[3]) * (1.0f / D_);
  float r = rsqrtf(var + 1e-5f);
  const float* w = isq ? qw : kw;
  xs[d] = x * r * w[d];
  __syncthreads();

  float c = g_cos[t * 64 + (d & 63)];
  float s = g_sin[t * 64 + (d & 63)];
  float o;
  if (d < 64) o = xs[d] * c - xs[d + 64] * s;
  else        o = xs[d] * c + xs[d - 64] * s;

  if (isq) qout[((size_t)t * H_ + head) * D_ + d] = o;
  else     kout[((size_t)t * HKV_ + (head - H_)) * D_ + d] = o;
}

// ---------------- bf16x3 flash attention ------------------------------------
// grid (T/64, H), 128 threads (4 warps x 16 query rows).
// smem: K hi/lo [64][136], V hi/lo [128][74] (transposed), 72704 B total.
#define KS_STR 136
#define VS_STR 74
#define ATTN_SMEM ((2 * 64 * KS_STR + 2 * 128 * VS_STR) * 2)
__global__ __launch_bounds__(128)
void attn_bf16_kernel(const float* __restrict__ Q,
                      const float* __restrict__ Kg,    // [t][kh][d]
                      const float* __restrict__ Vbase, // qkv v section
                      float* __restrict__ O) {
  extern __shared__ __nv_bfloat16 smh[];
  __nv_bfloat16* Ksh = smh;
  __nv_bfloat16* Ksl = Ksh + 64 * KS_STR;
  __nv_bfloat16* Vsh = Ksl + 64 * KS_STR;
  __nv_bfloat16* Vsl = Vsh + 128 * VS_STR;

  const int qb = blockIdx.x, h = blockIdx.y, kh = h >> 2;
  const int tid = threadIdx.x, lane = tid & 31, w = tid >> 5;
  const int gr = lane >> 2, cq = lane & 3;
  const int q0 = qb * 64;
  const int qi0 = q0 + w * 16 + gr, qi1 = qi0 + 8;
  const float scale = 0.08838834764831845f;

  // Q fragments, pre-scaled, split hi/lo
  uint32_t qh[8][4], ql[8][4];
  {
    const float* q0p = Q + ((size_t)qi0 * H_ + h) * D_;
    const float* q1p = Q + ((size_t)qi1 * H_ + h) * D_;
#pragma unroll
    for (int ks = 0; ks < 8; ks++) {
      int c = ks * 16 + cq * 2;
      float2 v00 = *(const float2*)(q0p + c);
      float2 v01 = *(const float2*)(q0p + c + 8);
      float2 v10 = *(const float2*)(q1p + c);
      float2 v11 = *(const float2*)(q1p + c + 8);
      __nv_bfloat16 ha, la, hb, lb;
      splitf(v00.x * scale, ha, la); splitf(v00.y * scale, hb, lb);
      qh[ks][0] = pk(ha, hb); ql[ks][0] = pk(la, lb);
      splitf(v10.x * scale, ha, la); splitf(v10.y * scale, hb, lb);
      qh[ks][1] = pk(ha, hb); ql[ks][1] = pk(la, lb);
      splitf(v01.x * scale, ha, la); splitf(v01.y * scale, hb, lb);
      qh[ks][2] = pk(ha, hb); ql[ks][2] = pk(la, lb);
      splitf(v11.x * scale, ha, la); splitf(v11.y * scale, hb, lb);
      qh[ks][3] = pk(ha, hb); ql[ks][3] = pk(la, lb);
    }
  }

  float accO[16][4];
#pragma unroll
  for (int nt = 0; nt < 16; nt++)
#pragma unroll
    for (int r = 0; r < 4; r++) accO[nt][r] = 0.f;
  float m0 = -1e30f, m1 = -1e30f, l0 = 0.f, l1 = 0.f;

  const int kb0 = (qb >= 16) ? (qb - 16) : 0;
  for (int kb = kb0; kb <= qb; kb++) {
    __syncthreads();
    const int k0 = kb * 64;
    // K tile -> Ks[key][d] hi/lo
    for (int e = tid; e < 2048; e += 128) {
      int key = e >> 5, dq = (e & 31) * 4;
      float4 v = *(const float4*)(Kg + ((size_t)(k0 + key) * HKV_ + kh) * D_ + dq);
      __nv_bfloat16 hx, lx, hy, ly, hz, lz, hw, lw;
      splitf(v.x, hx, lx); splitf(v.y, hy, ly);
      splitf(v.z, hz, lz); splitf(v.w, hw, lw);
      int b = key * KS_STR + dq;
      *(uint32_t*)&Ksh[b]     = pk(hx, hy);
      *(uint32_t*)&Ksh[b + 2] = pk(hz, hw);
      *(uint32_t*)&Ksl[b]     = pk(lx, ly);
      *(uint32_t*)&Ksl[b + 2] = pk(lz, lw);
    }
    // V tile -> Vs[d][key] hi/lo (transposed)
    for (int e = tid; e < 2048; e += 128) {
      int key = e >> 5, dq = (e & 31) * 4;
      float4 v = *(const float4*)(Vbase + (size_t)(k0 + key) * NQKV_ + kh * D_ + dq);
      __nv_bfloat16 hh, ll;
      splitf(v.x, hh, ll); Vsh[(dq + 0) * VS_STR + key] = hh; Vsl[(dq + 0) * VS_STR + key] = ll;
      splitf(v.y, hh, ll); Vsh[(dq + 1) * VS_STR + key] = hh; Vsl[(dq + 1) * VS_STR + key] = ll;
      splitf(v.z, hh, ll); Vsh[(dq + 2) * VS_STR + key] = hh; Vsl[(dq + 2) * VS_STR + key] = ll;
      splitf(v.w, hh, ll); Vsh[(dq + 3) * VS_STR + key] = hh; Vsl[(dq + 3) * VS_STR + key] = ll;
    }
    __syncthreads();

    // S = Q @ K^T
    float s[8][4];
#pragma unroll
    for (int nt = 0; nt < 8; nt++)
#pragma unroll
      for (int r = 0; r < 4; r++) s[nt][r] = 0.f;
#pragma unroll
    for (int ks = 0; ks < 8; ks++) {
#pragma unroll
      for (int nt = 0; nt < 8; nt++) {
        int base = (nt * 8 + gr) * KS_STR + ks * 16 + cq * 2;
        uint32_t bh[2] = {*(uint32_t*)&Ksh[base], *(uint32_t*)&Ksh[base + 8]};
        uint32_t bl[2] = {*(uint32_t*)&Ksl[base], *(uint32_t*)&Ksl[base + 8]};
        mma_bf16(s[nt], qh[ks], bh);
        mma_bf16(s[nt], qh[ks], bl);
        mma_bf16(s[nt], ql[ks], bh);
      }
    }

    // mask
#pragma unroll
    for (int nt = 0; nt < 8; nt++) {
#pragma unroll
      for (int j = 0; j < 4; j++) {
        int kj_g = k0 + nt * 8 + cq * 2 + (j & 1);
        int qi = (j < 2) ? qi0 : qi1;
        if (kj_g > qi || (qi - kj_g) >= WIN_) s[nt][j] = -1e30f;
      }
    }

    // online softmax
    float tm0 = -1e30f, tm1 = -1e30f;
#pragma unroll
    for (int nt = 0; nt < 8; nt++) {
      tm0 = fmaxf(tm0, fmaxf(s[nt][0], s[nt][1]));
      tm1 = fmaxf(tm1, fmaxf(s[nt][2], s[nt][3]));
    }
    tm0 = fmaxf(tm0, __shfl_xor_sync(0xffffffffu, tm0, 1));
    tm0 = fmaxf(tm0, __shfl_xor_sync(0xffffffffu, tm0, 2));
    tm1 = fmaxf(tm1, __shfl_xor_sync(0xffffffffu, tm1, 1));
    tm1 = fmaxf(tm1, __shfl_xor_sync(0xffffffffu, tm1, 2));
    float mn0 = fmaxf(m0, tm0), mn1 = fmaxf(m1, tm1);
    float sum0 = 0.f, sum1 = 0.f;
#pragma unroll
    for (int nt = 0; nt < 8; nt++) {
      s[nt][0] = __expf(s[nt][0] - mn0); sum0 += s[nt][0];
      s[nt][1] = __expf(s[nt][1] - mn0); sum0 += s[nt][1];
      s[nt][2] = __expf(s[nt][2] - mn1); sum1 += s[nt][2];
      s[nt][3] = __expf(s[nt][3] - mn1); sum1 += s[nt][3];
    }
    sum0 += __shfl_xor_sync(0xffffffffu, sum0, 1);
    sum0 += __shfl_xor_sync(0xffffffffu, sum0, 2);
    sum1 += __shfl_xor_sync(0xffffffffu, sum1, 1);
    sum1 += __shfl_xor_sync(0xffffffffu, sum1, 2);
    float sc0 = __expf(m0 - mn0), sc1 = __expf(m1 - mn1);
    l0 = l0 * sc0 + sum0; l1 = l1 * sc1 + sum1;
    m0 = mn0; m1 = mn1;
#pragma unroll
    for (int nt = 0; nt < 16; nt++) {
      accO[nt][0] *= sc0; accO[nt][1] *= sc0;
      accO[nt][2] *= sc1; accO[nt][3] *= sc1;
    }

    // O += P @ V  (P fragments built directly from S registers)
#pragma unroll
    for (int ks = 0; ks < 4; ks++) {
      uint32_t ph[4], pl[4];
      __nv_bfloat16 ha, la, hb, lb;
      splitf(s[2 * ks][0], ha, la); splitf(s[2 * ks][1], hb, lb);
      ph[0] = pk(ha, hb); pl[0] = pk(la, lb);
      splitf(s[2 * ks][2], ha, la); splitf(s[2 * ks][3], hb, lb);
      ph[1] = pk(ha, hb); pl[1] = pk(la, lb);
      splitf(s[2 * ks + 1][0], ha, la); splitf(s[2 * ks + 1][1], hb, lb);
      ph[2] = pk(ha, hb); pl[2] = pk(la, lb);
      splitf(s[2 * ks + 1][2], ha, la); splitf(s[2 * ks + 1][3], hb, lb);
      ph[3] = pk(ha, hb); pl[3] = pk(la, lb);
#pragma unroll
      for (int nt = 0; nt < 16; nt++) {
        int base = (nt * 8 + gr) * VS_STR + ks * 16 + cq * 2;
        uint32_t bh[2] = {*(uint32_t*)&Vsh[base], *(uint32_t*)&Vsh[base + 8]};
        uint32_t bl[2] = {*(uint32_t*)&Vsl[base], *(uint32_t*)&Vsl[base + 8]};
        mma_bf16(accO[nt], ph, bh);
        mma_bf16(accO[nt], ph, bl);
        mma_bf16(accO[nt], pl, bh);
      }
    }
  }

  // normalize + write
  float inv0 = 1.f / l0, inv1 = 1.f / l1;
  float* o0 = O + ((size_t)qi0 * H_ + h) * D_;
  float* o1 = O + ((size_t)qi1 * H_ + h) * D_;
#pragma unroll
  for (int nt = 0; nt < 16; nt++) {
    int c = nt * 8 + cq * 2;
    *(float2*)&o0[c] = make_float2(accO[nt][0] * inv0, accO[nt][1] * inv0);
    *(float2*)&o1[c] = make_float2(accO[nt][2] * inv1, accO[nt][3] * inv1);
  }
}

// ---------------- launch ---------------------------------------------------
extern "C" void kernel_launch(void* const* d_in, const int* in_sizes, int n_in,
                              void* d_out, int out_size) {
  const int*   positions = (const int*)  d_in[0];
  const float* hidden    = (const float*)d_in[1];
  const float* w_qkv     = (const float*)d_in[2];
  const float* q_norm_w  = (const float*)d_in[3];
  const float* k_norm_w  = (const float*)d_in[4];
  const float* w_o       = (const float*)d_in[5];
  float* out = (float*)d_out;

  float *qkv, *q, *k, *attn;
  cudaGetSymbolAddress((void**)&qkv,  g_qkv);
  cudaGetSymbolAddress((void**)&q,    g_q);
  cudaGetSymbolAddress((void**)&k,    g_k);
  cudaGetSymbolAddress((void**)&attn, g_attn);

  rope_table_kernel<<<T_, 64>>>(positions);
  bf16x3_gemm<<<dim3(NQKV_ / 128, T_ / 128), 256>>>(hidden, w_qkv, qkv,
                                                    T_, NQKV_, HID_);
  norm_rope_kernel<<<dim3(T_, H_ + HKV_), 128>>>(qkv, q_norm_w, k_norm_w,
                                                 q, k);
  cudaFuncSetAttribute(attn_bf16_kernel,
                       cudaFuncAttributeMaxDynamicSharedMemorySize, ATTN_SMEM);
  attn_bf16_kernel<<<dim3(T_ / 64, H_), 128, ATTN_SMEM>>>(
      q, k, qkv + (H_ + HKV_) * D_, attn);
  bf16x3_gemm<<<dim3(HID_ / 128, T_ / 128), 256>>>(attn, w_o, out,
                                                   T_, HID_, HID_);
}

// round 6
// speedup vs baseline: 2.9240x; 2.9240x over previous
#include <cuda_runtime.h>
#include <cuda_bf16.h>
#include <math.h>
#include <stdint.h>

#define T_    2048
#define HID_  4096
#define H_    32
#define HKV_  8
#define D_    128
#define NQKV_ 6144
#define WIN_  1024

// tcgen05 only exists in an arch-specific ('a') compilation pass.
#if defined(__CUDA_ARCH__) && (defined(__CUDA_ARCH_FEAT_SM103_ALL) || \
    defined(__CUDA_ARCH_SPECIFIC__) || defined(__CUDA_ARCH_FAMILY_SPECIFIC__))
#define TC_ARCH 1
#else
#define TC_ARCH 0
#endif

// ---------------- scratch ---------------------------------------------------
__device__ int   g_tc_ok;
__device__ float g_qkv [T_ * NQKV_];
__device__ float g_q   [T_ * H_ * D_];
__device__ float g_k   [T_ * HKV_ * D_];
__device__ float g_attn[T_ * H_ * D_];
__device__ float g_cos [T_ * 64];
__device__ float g_sin [T_ * 64];
__device__ __nv_bfloat16 g_bqh[NQKV_ * HID_];
__device__ __nv_bfloat16 g_bql[NQKV_ * HID_];
__device__ __nv_bfloat16 g_boh[HID_ * HID_];
__device__ __nv_bfloat16 g_bol[HID_ * HID_];
__device__ __nv_bfloat16 g_ah [T_ * HID_];
__device__ __nv_bfloat16 g_al [T_ * HID_];

__global__ void tc_probe() {
#if TC_ARCH
  g_tc_ok = 1;
#else
  g_tc_ok = 0;
#endif
}

// ---------------- helpers ---------------------------------------------------
__device__ __forceinline__ void splitf(float x, __nv_bfloat16& h,
                                       __nv_bfloat16& l) {
  h = __float2bfloat16(x);
  l = __float2bfloat16(x - __bfloat162float(h));
}
__device__ __forceinline__ uint32_t pk(__nv_bfloat16 a, __nv_bfloat16 b) {
  __nv_bfloat162 t(a, b);
  return *reinterpret_cast<uint32_t*>(&t);
}
__device__ __forceinline__ void mma_bf16(float* d, const uint32_t* a,
                                         const uint32_t* b) {
  asm volatile(
      "mma.sync.aligned.m16n8k16.row.col.f32.bf16.bf16.f32 "
      "{%0,%1,%2,%3}, {%4,%5,%6,%7}, {%8,%9}, {%0,%1,%2,%3};"
      : "+f"(d[0]), "+f"(d[1]), "+f"(d[2]), "+f"(d[3])
      : "r"(a[0]), "r"(a[1]), "r"(a[2]), "r"(a[3]), "r"(b[0]), "r"(b[1]));
}
__device__ __forceinline__ uint32_t f2tf32(float f) {
  uint32_t u;
  asm("cvt.rna.tf32.f32 %0, %1;" : "=r"(u) : "f"(f));
  return u;
}
__device__ __forceinline__ void mma_tf32(float* d, const uint32_t* a,
                                         const uint32_t* b) {
  asm volatile(
      "mma.sync.aligned.m16n8k8.row.col.f32.tf32.tf32.f32 "
      "{%0,%1,%2,%3}, {%4,%5,%6,%7}, {%8,%9}, {%0,%1,%2,%3};"
      : "+f"(d[0]), "+f"(d[1]), "+f"(d[2]), "+f"(d[3])
      : "r"(a[0]), "r"(a[1]), "r"(a[2]), "r"(a[3]), "r"(b[0]), "r"(b[1]));
}
__device__ __forceinline__ uint32_t smem_u32(const void* p) {
  uint32_t a;
  asm("{ .reg .u64 t; cvta.to.shared.u64 t, %1; cvt.u32.u64 %0, t; }"
      : "=r"(a) : "l"(p));
  return a;
}
__device__ __forceinline__ uint32_t elect1() {
  uint32_t p;
  asm volatile("{\n\t.reg .pred p;\n\telect.sync _|p, 0xFFFFFFFF;\n\t"
               "selp.b32 %0, 1, 0, p;\n\t}" : "=r"(p));
  return p;
}
#define MBAR_INIT(a, c) \
  asm volatile("mbarrier.init.shared.b64 [%0], %1;" :: "r"(a), "r"(c) : "memory")
#define MBAR_WAIT(a, ph) do {                                              \
  uint32_t _m = (a), _p = (ph), _d;                                        \
  asm volatile("{\n\t.reg .pred p;\n\t"                                    \
    "mbarrier.try_wait.parity.acquire.cta.shared::cta.b64 p, [%1], %2;\n\t"\
    "selp.b32 %0, 1, 0, p;\n\t}" : "=r"(_d) : "r"(_m), "r"(_p) : "memory");\
  if (!_d) {                                                               \
    asm volatile("{\n\t.reg .pred P1;\n\tWL_%=:\n\t"                       \
      "mbarrier.try_wait.parity.acquire.cta.shared::cta.b64 P1, [%0], %1, 0x989680;\n\t"\
      "@P1 bra.uni WD_%=;\n\tbra.uni WL_%=;\n\tWD_%=:\n\t}"                \
      :: "r"(_m), "r"(_p) : "memory");                                     \
  }                                                                        \
} while (0)
__device__ __forceinline__ void cp_async16(uint32_t dst, const void* src) {
  asm volatile("cp.async.cg.shared.global [%0], [%1], 16;\n"
               :: "r"(dst), "l"(src));
}
static constexpr uint64_t DESC_SW128 =
    (2ull << 61) | (1ull << 46) | (64ull << 32) | (1ull << 16);
__device__ __forceinline__ uint64_t mk_desc(uint32_t addr) {
  return DESC_SW128 | ((uint64_t)(addr >> 4) & 0x3FFF);
}
__device__ __forceinline__ void tc_mma_f16_ss(uint32_t d, uint64_t ad,
                                              uint64_t bd, uint32_t idesc,
                                              uint32_t en) {
#if TC_ARCH
  asm volatile(
      "{\n\t.reg .pred p;\n\tsetp.ne.u32 p, %5, 0;\n\t"
      "tcgen05.mma.cta_group::1.kind::f16 [%0], %1, %2, %3, {%4,%4,%4,%4}, p;\n\t}"
      :: "r"(d), "l"(ad), "l"(bd), "r"(idesc), "r"(0u), "r"(en) : "memory");
#endif
}
__device__ __forceinline__ void tc_ld32(uint32_t* r, uint32_t ta) {
#if TC_ARCH
  asm volatile(
      "tcgen05.ld.sync.aligned.32x32b.x32.b32 "
      "{%0,%1,%2,%3,%4,%5,%6,%7,%8,%9,%10,%11,%12,%13,%14,%15,"
      "%16,%17,%18,%19,%20,%21,%22,%23,%24,%25,%26,%27,%28,%29,%30,%31},[%32];"
      : "=r"(r[0]), "=r"(r[1]), "=r"(r[2]), "=r"(r[3]), "=r"(r[4]),
        "=r"(r[5]), "=r"(r[6]), "=r"(r[7]), "=r"(r[8]), "=r"(r[9]),
        "=r"(r[10]), "=r"(r[11]), "=r"(r[12]), "=r"(r[13]), "=r"(r[14]),
        "=r"(r[15]), "=r"(r[16]), "=r"(r[17]), "=r"(r[18]), "=r"(r[19]),
        "=r"(r[20]), "=r"(r[21]), "=r"(r[22]), "=r"(r[23]), "=r"(r[24]),
        "=r"(r[25]), "=r"(r[26]), "=r"(r[27]), "=r"(r[28]), "=r"(r[29]),
        "=r"(r[30]), "=r"(r[31])
      : "r"(ta));
#endif
}

// ---------------- pre-passes (only needed when tcgen05 is live) -------------
__global__ void split_mat(const float* __restrict__ in,
                          __nv_bfloat16* __restrict__ oh,
                          __nv_bfloat16* __restrict__ ol) {
  if (!*(volatile int*)&g_tc_ok) return;
  int i = blockIdx.x * 256 + threadIdx.x;
  float4 v = ((const float4*)in)[i];
  __nv_bfloat16 h0, l0, h1, l1, h2, l2, h3, l3;
  splitf(v.x, h0, l0); splitf(v.y, h1, l1);
  splitf(v.z, h2, l2); splitf(v.w, h3, l3);
  ((uint32_t*)oh)[i * 2]     = pk(h0, h1);
  ((uint32_t*)oh)[i * 2 + 1] = pk(h2, h3);
  ((uint32_t*)ol)[i * 2]     = pk(l0, l1);
  ((uint32_t*)ol)[i * 2 + 1] = pk(l2, l3);
}

__global__ void transpose_split(const float* __restrict__ in,
                                __nv_bfloat16* __restrict__ oh,
                                __nv_bfloat16* __restrict__ ol,
                                int Kd, int Nd) {
  if (!*(volatile int*)&g_tc_ok) return;
  __shared__ float t[32][33];
  int n0 = blockIdx.x * 32, k0 = blockIdx.y * 32;
  int tx = threadIdx.x, ty = threadIdx.y;
#pragma unroll
  for (int i = 0; i < 4; i++)
    t[ty + i * 8][tx] = in[(size_t)(k0 + ty + i * 8) * Nd + n0 + tx];
  __syncthreads();
#pragma unroll
  for (int i = 0; i < 4; i++) {
    float v = t[tx][ty + i * 8];
    __nv_bfloat16 h, l;
    splitf(v, h, l);
    oh[(size_t)(n0 + ty + i * 8) * Kd + k0 + tx] = h;
    ol[(size_t)(n0 + ty + i * 8) * Kd + k0 + tx] = l;
  }
}

// ---------------- tcgen05 bf16x3 GEMM (no-op unless TC_ARCH) ----------------
#define G_STAGE 65536
#define G_SMEM  (1024 + 2 * G_STAGE)
__global__ __launch_bounds__(128)
void tc_gemm(const __nv_bfloat16* __restrict__ Ah,
             const __nv_bfloat16* __restrict__ Al,
             const __nv_bfloat16* __restrict__ Bh,
             const __nv_bfloat16* __restrict__ Bl,
             float* __restrict__ C, int M, int N, int K) {
#if TC_ARCH
  extern __shared__ char sm[];
  uint32_t smb = smem_u32(sm);
  const int tid = threadIdx.x, wid = tid >> 5, lane = tid & 31;
  const int cRow = blockIdx.y * 128, cCol = blockIdx.x * 128;

  if (tid == 0) { MBAR_INIT(smb + 8, 1); MBAR_INIT(smb + 16, 1); }
  if (wid == 0) {
    asm volatile(
        "tcgen05.alloc.cta_group::1.sync.aligned.shared::cta.b32 [%0], %1;"
        :: "r"(smb), "r"(128u) : "memory");
  }
  __syncthreads();
  uint32_t tmem;
  asm volatile("ld.shared.b32 %0, [%1];" : "=r"(tmem) : "r"(smb));

  const uint32_t idesc = (1u << 4) | (1u << 7) | (1u << 10) |
                         ((128u / 8) << 17) | ((128u / 16) << 24);
  const int nst = K >> 6;
  int wp0 = 0, wp1 = 0;

  for (int s = 0; s < nst; s++) {
    const int b = s & 1;
    if (s >= 2) {
      if (b == 0) { MBAR_WAIT(smb + 8, wp0);  wp0 ^= 1; }
      else        { MBAR_WAIT(smb + 16, wp1); wp1 ^= 1; }
    }
    const uint32_t tb = smb + 1024 + b * G_STAGE;
    const int k0 = s << 6;
#pragma unroll
    for (int tt = 0; tt < 4; tt++) {
      const __nv_bfloat16* src = (tt == 0) ? Ah : (tt == 1) ? Al
                               : (tt == 2) ? Bh : Bl;
      const int rb = (tt < 2) ? cRow : cCol;
      const uint32_t dstb = tb + tt * 16384;
#pragma unroll
      for (int i = 0; i < 8; i++) {
        int c = tid + i * 128;
        int r = c >> 3, c16 = c & 7;
        uint32_t off = (uint32_t)(r * 128 + c16 * 16);
        uint32_t sw = off ^ ((off >> 3) & 0x70);
        cp_async16(dstb + sw, src + (size_t)(rb + r) * K + k0 + c16 * 8);
      }
    }
    asm volatile("cp.async.commit_group;\n" ::: "memory");
    asm volatile("cp.async.wait_group 0;\n" ::: "memory");
    asm volatile("fence.proxy.async.shared::cta;" ::: "memory");
    __syncthreads();
    if (wid == 0 && elect1()) {
      uint64_t adh = mk_desc(tb), adl = mk_desc(tb + 16384);
      uint64_t bdh = mk_desc(tb + 32768), bdl = mk_desc(tb + 49152);
#pragma unroll
      for (int ks = 0; ks < 4; ks++) {
        uint64_t o = ks * 2;
        tc_mma_f16_ss(tmem, adh + o, bdh + o, idesc,
                      (s == 0 && ks == 0) ? 0u : 1u);
        tc_mma_f16_ss(tmem, adh + o, bdl + o, idesc, 1u);
        tc_mma_f16_ss(tmem, adl + o, bdh + o, idesc, 1u);
      }
      asm volatile(
          "tcgen05.commit.cta_group::1.mbarrier::arrive::one.shared::cluster.b64 [%0];"
          :: "r"(smb + 8 + b * 8) : "memory");
    }
  }
  MBAR_WAIT(smb + 8, wp0);
  if (nst > 1) MBAR_WAIT(smb + 16, wp1);
  asm volatile("tcgen05.fence::after_thread_sync;" ::: "memory");

  const int row = cRow + wid * 32 + lane;
#pragma unroll
  for (int cb = 0; cb < 128; cb += 32) {
    uint32_t r[32];
    tc_ld32(r, tmem + cb);
    asm volatile("tcgen05.wait::ld.sync.aligned;" ::: "memory");
    float* cp = C + (size_t)row * N + cCol + cb;
#pragma unroll
    for (int j = 0; j < 32; j += 4)
      *(float4*)(cp + j) =
          make_float4(__uint_as_float(r[j]), __uint_as_float(r[j + 1]),
                      __uint_as_float(r[j + 2]), __uint_as_float(r[j + 3]));
  }
  __syncthreads();
  if (wid == 0) {
    asm volatile("tcgen05.dealloc.cta_group::1.sync.aligned.b32 %0, %1;"
                 :: "r"(tmem), "r"(128u));
  }
#endif
}

// ---------------- tf32 fallback GEMM (early-exits when tcgen05 is live) -----
__global__ __launch_bounds__(256, 2)
void tf32_gemm(const float* __restrict__ A, const float* __restrict__ B,
               float* __restrict__ C, int M, int N, int K) {
  if (*(volatile int*)&g_tc_ok) return;
  __shared__ uint32_t As[128][36];
  __shared__ uint32_t Bs[32][132];
  const int tid  = threadIdx.x;
  const int lane = tid & 31;
  const int warp = tid >> 5;
  const int wm   = warp & 1;
  const int wn   = warp >> 1;
  const int cRow = blockIdx.y * 128;
  const int cCol = blockIdx.x * 128;

  float acc[4][4][4];
#pragma unroll
  for (int mt = 0; mt < 4; mt++)
#pragma unroll
    for (int nt = 0; nt < 4; nt++)
#pragma unroll
      for (int r = 0; r < 4; r++) acc[mt][nt][r] = 0.f;

  const int aRow = tid >> 1, aCol = (tid & 1) * 16;
  const int bRow = tid >> 3, bCol = (tid & 7) * 16;
  const float* Ap = A + (size_t)(cRow + aRow) * K + aCol;
  const float* Bp = B + (size_t)bRow * N + cCol + bCol;

  for (int k0 = 0; k0 < K; k0 += 32) {
#pragma unroll
    for (int i = 0; i < 4; i++) {
      float4 v = *(const float4*)(Ap + k0 + i * 4);
      As[aRow][aCol + i * 4 + 0] = f2tf32(v.x);
      As[aRow][aCol + i * 4 + 1] = f2tf32(v.y);
      As[aRow][aCol + i * 4 + 2] = f2tf32(v.z);
      As[aRow][aCol + i * 4 + 3] = f2tf32(v.w);
    }
#pragma unroll
    for (int i = 0; i < 4; i++) {
      float4 v = *(const float4*)(Bp + (size_t)k0 * N + i * 4);
      Bs[bRow][bCol + i * 4 + 0] = f2tf32(v.x);
      Bs[bRow][bCol + i * 4 + 1] = f2tf32(v.y);
      Bs[bRow][bCol + i * 4 + 2] = f2tf32(v.z);
      Bs[bRow][bCol + i * 4 + 3] = f2tf32(v.w);
    }
    __syncthreads();
#pragma unroll
    for (int ks = 0; ks < 4; ks++) {
      uint32_t af[4][4], bf[4][2];
#pragma unroll
      for (int mt = 0; mt < 4; mt++) {
        int r = wm * 64 + mt * 16 + (lane >> 2);
        int c = ks * 8 + (lane & 3);
        af[mt][0] = As[r][c];
        af[mt][1] = As[r + 8][c];
        af[mt][2] = As[r][c + 4];
        af[mt][3] = As[r + 8][c + 4];
      }
#pragma unroll
      for (int nt = 0; nt < 4; nt++) {
        int r = ks * 8 + (lane & 3);
        int c = wn * 32 + nt * 8 + (lane >> 2);
        bf[nt][0] = Bs[r][c];
        bf[nt][1] = Bs[r + 4][c];
      }
#pragma unroll
      for (int mt = 0; mt < 4; mt++)
#pragma unroll
        for (int nt = 0; nt < 4; nt++) mma_tf32(acc[mt][nt], af[mt], bf[nt]);
    }
    __syncthreads();
  }

#pragma unroll
  for (int mt = 0; mt < 4; mt++) {
    int r = cRow + wm * 64 + mt * 16 + (lane >> 2);
#pragma unroll
    for (int nt = 0; nt < 4; nt++) {
      int c = cCol + wn * 32 + nt * 8 + (lane & 3) * 2;
      *(float2*)&C[(size_t)r * N + c] =
          make_float2(acc[mt][nt][0], acc[mt][nt][1]);
      *(float2*)&C[(size_t)(r + 8) * N + c] =
          make_float2(acc[mt][nt][2], acc[mt][nt][3]);
    }
  }
}

// ---------------- RoPE table ------------------------------------------------
__global__ void rope_table_kernel(const int* __restrict__ positions) {
  int t = blockIdx.x, i = threadIdx.x;
  double inv_freq = pow(1000000.0, -(double)i / 64.0);
  double ang = (double)positions[t] * inv_freq;
  double sd, cd;
  sincos(ang, &sd, &cd);
  g_cos[t * 64 + i] = (float)cd;
  g_sin[t * 64 + i] = (float)sd;
}

// ---------------- fused RMSNorm + NeoX RoPE --------------------------------
__global__ void norm_rope_kernel(const float* __restrict__ qkv,
                                 const float* __restrict__ qw,
                                 const float* __restrict__ kw,
                                 float* __restrict__ qout,
                                 float* __restrict__ kout) {
  const int t = blockIdx.x, head = blockIdx.y, d = threadIdx.x;
  const bool isq = head < H_;
  float x = qkv[(size_t)t * NQKV_ + head * D_ + d];

  __shared__ float red[4];
  __shared__ float xs[D_];
  float ss = x * x;
#pragma unroll
  for (int m = 16; m; m >>= 1) ss += __shfl_xor_sync(0xffffffffu, ss, m);
  if ((d & 31) == 0) red[d >> 5] = ss;
  __syncthreads();
  float var = (red[0] + red[1] + red[2] + red[3]) * (1.0f / D_);
  float r = rsqrtf(var + 1e-5f);
  const float* w = isq ? qw : kw;
  xs[d] = x * r * w[d];
  __syncthreads();

  float c = g_cos[t * 64 + (d & 63)];
  float s = g_sin[t * 64 + (d & 63)];
  float o;
  if (d < 64) o = xs[d] * c - xs[d + 64] * s;
  else        o = xs[d] * c + xs[d - 64] * s;

  if (isq) qout[((size_t)t * H_ + head) * D_ + d] = o;
  else     kout[((size_t)t * HKV_ + (head - H_)) * D_ + d] = o;
}

// ---------------- bf16x3 flash attention (R3, known-good) -------------------
#define KS_STR 136
#define VS_STR 74
#define ATTN_SMEM ((2 * 64 * KS_STR + 2 * 128 * VS_STR) * 2)
__global__ __launch_bounds__(128)
void attn_bf16_kernel(const float* __restrict__ Q,
                      const float* __restrict__ Kg,
                      const float* __restrict__ Vbase,
                      float* __restrict__ O) {
  extern __shared__ __nv_bfloat16 smh[];
  __nv_bfloat16* Ksh = smh;
  __nv_bfloat16* Ksl = Ksh + 64 * KS_STR;
  __nv_bfloat16* Vsh = Ksl + 64 * KS_STR;
  __nv_bfloat16* Vsl = Vsh + 128 * VS_STR;

  const int qb = blockIdx.x, h = blockIdx.y, kh = h >> 2;
  const int tid = threadIdx.x, lane = tid & 31, w = tid >> 5;
  const int gr = lane >> 2, cq = lane & 3;
  const int q0 = qb * 64;
  const int qi0 = q0 + w * 16 + gr, qi1 = qi0 + 8;
  const float scale = 0.08838834764831845f;

  uint32_t qh[8][4], ql[8][4];
  {
    const float* q0p = Q + ((size_t)qi0 * H_ + h) * D_;
    const float* q1p = Q + ((size_t)qi1 * H_ + h) * D_;
#pragma unroll
    for (int ks = 0; ks < 8; ks++) {
      int c = ks * 16 + cq * 2;
      float2 v00 = *(const float2*)(q0p + c);
      float2 v01 = *(const float2*)(q0p + c + 8);
      float2 v10 = *(const float2*)(q1p + c);
      float2 v11 = *(const float2*)(q1p + c + 8);
      __nv_bfloat16 ha, la, hb, lb;
      splitf(v00.x * scale, ha, la); splitf(v00.y * scale, hb, lb);
      qh[ks][0] = pk(ha, hb); ql[ks][0] = pk(la, lb);
      splitf(v10.x * scale, ha, la); splitf(v10.y * scale, hb, lb);
      qh[ks][1] = pk(ha, hb); ql[ks][1] = pk(la, lb);
      splitf(v01.x * scale, ha, la); splitf(v01.y * scale, hb, lb);
      qh[ks][2] = pk(ha, hb); ql[ks][2] = pk(la, lb);
      splitf(v11.x * scale, ha, la); splitf(v11.y * scale, hb, lb);
      qh[ks][3] = pk(ha, hb); ql[ks][3] = pk(la, lb);
    }
  }

  float accO[16][4];
#pragma unroll
  for (int nt = 0; nt < 16; nt++)
#pragma unroll
    for (int r = 0; r < 4; r++) accO[nt][r] = 0.f;
  float m0 = -1e30f, m1 = -1e30f, l0 = 0.f, l1 = 0.f;

  const int kb0 = (qb >= 16) ? (qb - 16) : 0;
  for (int kb = kb0; kb <= qb; kb++) {
    __syncthreads();
    const int k0 = kb * 64;
    for (int e = tid; e < 2048; e += 128) {
      int key = e >> 5, dq = (e & 31) * 4;
      float4 v = *(const float4*)(Kg + ((size_t)(k0 + key) * HKV_ + kh) * D_ + dq);
      __nv_bfloat16 hx, lx, hy, ly, hz, lz, hw, lw;
      splitf(v.x, hx, lx); splitf(v.y, hy, ly);
      splitf(v.z, hz, lz); splitf(v.w, hw, lw);
      int b = key * KS_STR + dq;
      *(uint32_t*)&Ksh[b]     = pk(hx, hy);
      *(uint32_t*)&Ksh[b + 2] = pk(hz, hw);
      *(uint32_t*)&Ksl[b]     = pk(lx, ly);
      *(uint32_t*)&Ksl[b + 2] = pk(lz, lw);
    }
    for (int e = tid; e < 2048; e += 128) {
      int key = e >> 5, dq = (e & 31) * 4;
      float4 v = *(const float4*)(Vbase + (size_t)(k0 + key) * NQKV_ + kh * D_ + dq);
      __nv_bfloat16 hh, ll;
      splitf(v.x, hh, ll); Vsh[(dq + 0) * VS_STR + key] = hh; Vsl[(dq + 0) * VS_STR + key] = ll;
      splitf(v.y, hh, ll); Vsh[(dq + 1) * VS_STR + key] = hh; Vsl[(dq + 1) * VS_STR + key] = ll;
      splitf(v.z, hh, ll); Vsh[(dq + 2) * VS_STR + key] = hh; Vsl[(dq + 2) * VS_STR + key] = ll;
      splitf(v.w, hh, ll); Vsh[(dq + 3) * VS_STR + key] = hh; Vsl[(dq + 3) * VS_STR + key] = ll;
    }
    __syncthreads();

    float s[8][4];
#pragma unroll
    for (int nt = 0; nt < 8; nt++)
#pragma unroll
      for (int r = 0; r < 4; r++) s[nt][r] = 0.f;
#pragma unroll
    for (int ks = 0; ks < 8; ks++) {
#pragma unroll
      for (int nt = 0; nt < 8; nt++) {
        int base = (nt * 8 + gr) * KS_STR + ks * 16 + cq * 2;
        uint32_t bh[2] = {*(uint32_t*)&Ksh[base], *(uint32_t*)&Ksh[base + 8]};
        uint32_t bl[2] = {*(uint32_t*)&Ksl[base], *(uint32_t*)&Ksl[base + 8]};
        mma_bf16(s[nt], qh[ks], bh);
        mma_bf16(s[nt], qh[ks], bl);
        mma_bf16(s[nt], ql[ks], bh);
      }
    }

#pragma unroll
    for (int nt = 0; nt < 8; nt++) {
#pragma unroll
      for (int j = 0; j < 4; j++) {
        int kj_g = k0 + nt * 8 + cq * 2 + (j & 1);
        int qi = (j < 2) ? qi0 : qi1;
        if (kj_g > qi || (qi - kj_g) >= WIN_) s[nt][j] = -1e30f;
      }
    }

    float tm0 = -1e30f, tm1 = -1e30f;
#pragma unroll
    for (int nt = 0; nt < 8; nt++) {
      tm0 = fmaxf(tm0, fmaxf(s[nt][0], s[nt][1]));
      tm1 = fmaxf(tm1, fmaxf(s[nt][2], s[nt][3]));
    }
    tm0 = fmaxf(tm0, __shfl_xor_sync(0xffffffffu, tm0, 1));
    tm0 = fmaxf(tm0, __shfl_xor_sync(0xffffffffu, tm0, 2));
    tm1 = fmaxf(tm1, __shfl_xor_sync(0xffffffffu, tm1, 1));
    tm1 = fmaxf(tm1, __shfl_xor_sync(0xffffffffu, tm1, 2));
    float mn0 = fmaxf(m0, tm0), mn1 = fmaxf(m1, tm1);
    float sum0 = 0.f, sum1 = 0.f;
#pragma unroll
    for (int nt = 0; nt < 8; nt++) {
      s[nt][0] = __expf(s[nt][0] - mn0); sum0 += s[nt][0];
      s[nt][1] = __expf(s[nt][1] - mn0); sum0 += s[nt][1];
      s[nt][2] = __expf(s[nt][2] - mn1); sum1 += s[nt][2];
      s[nt][3] = __expf(s[nt][3] - mn1); sum1 += s[nt][3];
    }
    sum0 += __shfl_xor_sync(0xffffffffu, sum0, 1);
    sum0 += __shfl_xor_sync(0xffffffffu, sum0, 2);
    sum1 += __shfl_xor_sync(0xffffffffu, sum1, 1);
    sum1 += __shfl_xor_sync(0xffffffffu, sum1, 2);
    float sc0 = __expf(m0 - mn0), sc1 = __expf(m1 - mn1);
    l0 = l0 * sc0 + sum0; l1 = l1 * sc1 + sum1;
    m0 = mn0; m1 = mn1;
#pragma unroll
    for (int nt = 0; nt < 16; nt++) {
      accO[nt][0] *= sc0; accO[nt][1] *= sc0;
      accO[nt][2] *= sc1; accO[nt][3] *= sc1;
    }

#pragma unroll
    for (int ks = 0; ks < 4; ks++) {
      uint32_t ph[4], pl[4];
      __nv_bfloat16 ha, la, hb, lb;
      splitf(s[2 * ks][0], ha, la); splitf(s[2 * ks][1], hb, lb);
      ph[0] = pk(ha, hb); pl[0] = pk(la, lb);
      splitf(s[2 * ks][2], ha, la); splitf(s[2 * ks][3], hb, lb);
      ph[1] = pk(ha, hb); pl[1] = pk(la, lb);
      splitf(s[2 * ks + 1][0], ha, la); splitf(s[2 * ks + 1][1], hb, lb);
      ph[2] = pk(ha, hb); pl[2] = pk(la, lb);
      splitf(s[2 * ks + 1][2], ha, la); splitf(s[2 * ks + 1][3], hb, lb);
      ph[3] = pk(ha, hb); pl[3] = pk(la, lb);
#pragma unroll
      for (int nt = 0; nt < 16; nt++) {
        int base = (nt * 8 + gr) * VS_STR + ks * 16 + cq * 2;
        uint32_t bh[2] = {*(uint32_t*)&Vsh[base], *(uint32_t*)&Vsh[base + 8]};
        uint32_t bl[2] = {*(uint32_t*)&Vsl[base], *(uint32_t*)&Vsl[base + 8]};
        mma_bf16(accO[nt], ph, bh);
        mma_bf16(accO[nt], ph, bl);
        mma_bf16(accO[nt], pl, bh);
      }
    }
  }

  float inv0 = 1.f / l0, inv1 = 1.f / l1;
  float* o0 = O + ((size_t)qi0 * H_ + h) * D_;
  float* o1 = O + ((size_t)qi1 * H_ + h) * D_;
#pragma unroll
  for (int nt = 0; nt < 16; nt++) {
    int c = nt * 8 + cq * 2;
    *(float2*)&o0[c] = make_float2(accO[nt][0] * inv0, accO[nt][1] * inv0);
    *(float2*)&o1[c] = make_float2(accO[nt][2] * inv1, accO[nt][3] * inv1);
  }
}

// ---------------- launch ---------------------------------------------------
extern "C" void kernel_launch(void* const* d_in, const int* in_sizes, int n_in,
                              void* d_out, int out_size) {
  const int*   positions = (const int*)  d_in[0];
  const float* hidden    = (const float*)d_in[1];
  const float* w_qkv     = (const float*)d_in[2];
  const float* q_norm_w  = (const float*)d_in[3];
  const float* k_norm_w  = (const float*)d_in[4];
  const float* w_o       = (const float*)d_in[5];
  float* out = (float*)d_out;

  float *qkv, *q, *k, *attn;
  __nv_bfloat16 *bqh, *bql, *boh, *bol, *ah, *al;
  cudaGetSymbolAddress((void**)&qkv,  g_qkv);
  cudaGetSymbolAddress((void**)&q,    g_q);
  cudaGetSymbolAddress((void**)&k,    g_k);
  cudaGetSymbolAddress((void**)&attn, g_attn);
  cudaGetSymbolAddress((void**)&bqh,  g_bqh);
  cudaGetSymbolAddress((void**)&bql,  g_bql);
  cudaGetSymbolAddress((void**)&boh,  g_boh);
  cudaGetSymbolAddress((void**)&bol,  g_bol);
  cudaGetSymbolAddress((void**)&ah,   g_ah);
  cudaGetSymbolAddress((void**)&al,   g_al);

  cudaFuncSetAttribute(tc_gemm, cudaFuncAttributeMaxDynamicSharedMemorySize,
                       G_SMEM);
  cudaFuncSetAttribute(attn_bf16_kernel,
                       cudaFuncAttributeMaxDynamicSharedMemorySize, ATTN_SMEM);

  tc_probe<<<1, 1>>>();
  rope_table_kernel<<<T_, 64>>>(positions);
  transpose_split<<<dim3(NQKV_ / 32, HID_ / 32), dim3(32, 8)>>>(
      w_qkv, bqh, bql, HID_, NQKV_);
  transpose_split<<<dim3(HID_ / 32, HID_ / 32), dim3(32, 8)>>>(
      w_o, boh, bol, HID_, HID_);
  split_mat<<<T_ * HID_ / 4 / 256, 256>>>(hidden, ah, al);

  // 1) qkv = hidden @ w_qkv   (tcgen05 if available, else tf32 fallback)
  tc_gemm<<<dim3(NQKV_ / 128, T_ / 128), 128, G_SMEM>>>(
      ah, al, bqh, bql, qkv, T_, NQKV_, HID_);
  tf32_gemm<<<dim3(NQKV_ / 128, T_ / 128), 256>>>(hidden, w_qkv, qkv,
                                                  T_, NQKV_, HID_);
  // 2) rmsnorm + rope
  norm_rope_kernel<<<dim3(T_, H_ + HKV_), 128>>>(qkv, q_norm_w, k_norm_w,
                                                 q, k);
  // 3) attention
  attn_bf16_kernel<<<dim3(T_ / 64, H_), 128, ATTN_SMEM>>>(
      q, k, qkv + (H_ + HKV_) * D_, attn);
  // 4) out = attn @ w_o
  split_mat<<<T_ * HID_ / 4 / 256, 256>>>(attn, ah, al);
  tc_gemm<<<dim3(HID_ / 128, T_ / 128), 128, G_SMEM>>>(
      ah, al, boh, bol, out, T_, HID_, HID_);
  tf32_gemm<<<dim3(HID_ / 128, T_ / 128), 256>>>(attn, w_o, out,
                                                 T_, HID_, HID_);
}